// round 14
// baseline (speedup 1.0000x reference)
#include <cuda_runtime.h>
#include <cuda_fp16.h>

#define BQ     32
#define BD     512
#define EDIM   300
#define NK     11
#define DCH    64             // doc rows per pipeline stage
#define NST    (BD / DCH)     // 8 stages
#define RSH    312            // halfs per row (624 B = 39 granules, odd -> conflict-free)
#define RSB    (RSH * 2)      // bytes per row
#define KSTEPS 19             // K padded 300 -> 304 = 19*16
#define NTH    256

#define K50L2E   72.1347520f   //  50*log2(e)
#define C_B      129.8425536f  // 144.269504*0.9
#define C_R      28.8539008f   // 144.269504*0.2
#define C_RC     23.0831206f   // 28.8539008*0.9 - 2.88539008
#define C_TC0    58.4291492f   // 72.134752*0.81
#define C_STEP   0.0183156389f // e^-4

__device__ __forceinline__ float warp_sum(float v) {
    v += __shfl_xor_sync(0xffffffffu, v, 16);
    v += __shfl_xor_sync(0xffffffffu, v, 8);
    v += __shfl_xor_sync(0xffffffffu, v, 4);
    v += __shfl_xor_sync(0xffffffffu, v, 2);
    v += __shfl_xor_sync(0xffffffffu, v, 1);
    return v;
}

__device__ __forceinline__ unsigned sm_u32(const void* p) {
    unsigned r;
    asm("{ .reg .u64 t; cvta.to.shared.u64 t, %1; cvt.u32.u64 %0, t; }"
        : "=r"(r) : "l"(p));
    return r;
}

__device__ __forceinline__ float ex2(float x) {
    float r;
    asm("ex2.approx.f32 %0, %1;" : "=f"(r) : "f"(x));
    return r;
}

__device__ __forceinline__ void ldmx4(unsigned a, unsigned& r0, unsigned& r1,
                                      unsigned& r2, unsigned& r3) {
    asm volatile("ldmatrix.sync.aligned.m8n8.x4.shared.b16 {%0,%1,%2,%3}, [%4];"
                 : "=r"(r0), "=r"(r1), "=r"(r2), "=r"(r3) : "r"(a));
}

__device__ __forceinline__ void mma16816(float* C, unsigned a0, unsigned a1,
                                         unsigned a2, unsigned a3,
                                         unsigned b0, unsigned b1) {
    asm volatile("mma.sync.aligned.m16n8k16.row.col.f32.f16.f16.f32 "
                 "{%0,%1,%2,%3},{%4,%5,%6,%7},{%8,%9},{%0,%1,%2,%3};"
                 : "+f"(C[0]), "+f"(C[1]), "+f"(C[2]), "+f"(C[3])
                 : "r"(a0), "r"(a1), "r"(a2), "r"(a3), "r"(b0), "r"(b1));
}

// Fused load: fp32 row -> fp16 smem row, ssq computed from register data.
__device__ __forceinline__ float load_row_h(const float* __restrict__ emb, int tok,
                                            unsigned* dstRow, int lane) {
    const float4* src = reinterpret_cast<const float4*>(emb) + (size_t)tok * (EDIM / 4);
    uint2* d8 = reinterpret_cast<uint2*>(dstRow);
    float ssq = 0.0f;
    float4 v;
    __half2 h0, h1;
    uint2 pk;

    v = src[lane];
    ssq += v.x*v.x + v.y*v.y + v.z*v.z + v.w*v.w;
    h0 = __floats2half2_rn(v.x, v.y); h1 = __floats2half2_rn(v.z, v.w);
    pk.x = *reinterpret_cast<unsigned*>(&h0); pk.y = *reinterpret_cast<unsigned*>(&h1);
    d8[lane] = pk;

    v = src[lane + 32];
    ssq += v.x*v.x + v.y*v.y + v.z*v.z + v.w*v.w;
    h0 = __floats2half2_rn(v.x, v.y); h1 = __floats2half2_rn(v.z, v.w);
    pk.x = *reinterpret_cast<unsigned*>(&h0); pk.y = *reinterpret_cast<unsigned*>(&h1);
    d8[lane + 32] = pk;

    if (lane < 11) {   // 75 float4 per row = 32 + 32 + 11
        v = src[lane + 64];
        ssq += v.x*v.x + v.y*v.y + v.z*v.z + v.w*v.w;
        h0 = __floats2half2_rn(v.x, v.y); h1 = __floats2half2_rn(v.z, v.w);
        pk.x = *reinterpret_cast<unsigned*>(&h0); pk.y = *reinterpret_cast<unsigned*>(&h1);
        d8[lane + 64] = pk;
    }
    return ssq;
}

// RBF via two telescoping Gaussian chains, 4 ex2; kernel 0 = exact token match.
__device__ __forceinline__ void rbf_acc(float c, float rqv, int tq, float rdv, int td,
                                        float* kacc) {
    const bool ok = (tq > 0) && (td > 0);
    if (ok && (tq == td)) kacc[0] += 1.0f;
    const float m    = c * (rqv * rdv);
    const float bias = ok ? -C_TC0 : -12000.0f;
    const float A258 = fmaf(-K50L2E * m, m, bias);
    float tA = ex2(fmaf( C_B, m, A258));
    float tB = ex2(fmaf(-C_B, m, A258));
    float rA = ex2(fmaf(-C_R, m, C_RC));
    float rB = ex2(fmaf( C_R, m, C_RC));
    kacc[1]  += tA;            kacc[10] += tB;
    tA *= rA;                  tB *= rB;
    kacc[2]  += tA;            kacc[9]  += tB;
    rA *= C_STEP;              rB *= C_STEP;
    tA *= rA;                  tB *= rB;
    kacc[3]  += tA;            kacc[8]  += tB;
    rA *= C_STEP;              rB *= C_STEP;
    tA *= rA;                  tB *= rB;
    kacc[4]  += tA;            kacc[7]  += tB;
    rA *= C_STEP;              rB *= C_STEP;
    tA *= rA;                  tB *= rB;
    kacc[5]  += tA;            kacc[6]  += tB;
}

__global__ __launch_bounds__(NTH, 2)
void knrm_kernel(const int* __restrict__ qt,
                 const int* __restrict__ dt,
                 const float* __restrict__ emb,
                 const float* __restrict__ fcw,
                 const float* __restrict__ fcb,
                 float* __restrict__ out)
{
    extern __shared__ __align__(16) unsigned char smraw[];
    __half* dH  = reinterpret_cast<__half*>(smraw);        // [2*DCH][RSH] (2 buffers)
    __half* qH  = dH + 2 * DCH * RSH;                      // [BQ][RSH]
    float*  rq  = reinterpret_cast<float*>(qH + BQ * RSH); // [BQ]
    float*  rd  = rq + BQ;                                 // [2*DCH]
    int*    qtok = reinterpret_cast<int*>(rd + 2 * DCH);   // [BQ]
    int*    dtok = qtok + BQ;                              // [2*DCH]
    float*  qk  = reinterpret_cast<float*>(dtok + 2 * DCH);// [BQ][NK]

    const int b    = blockIdx.x;
    const int tid  = threadIdx.x;
    const int lane = tid & 31;
    const int warp = tid >> 5;          // 0..7
    const bool consumer = (warp < 4);

    for (int i = tid; i < BQ * NK; i += NTH) qk[i] = 0.0f;

    // zero K-pad (halfs 300..311) for all 160 rows (2 doc buffers + q)
    for (int i = tid; i < (2 * DCH + BQ) * 3; i += NTH) {
        const int row = i / 3, j = i - row * 3;
        unsigned* base = (row < 2 * DCH) ? reinterpret_cast<unsigned*>(dH)
                                         : reinterpret_cast<unsigned*>(qH);
        const int r2 = (row < 2 * DCH) ? row : row - 2 * DCH;
        base[r2 * (RSH / 2) + 150 + j] = 0u;
    }

    // ---- prologue (overlapped): consumers load 32 q rows, producers load stage 0 ----
    if (consumer) {
        #pragma unroll
        for (int r = 0; r < BQ / 4; ++r) {
            const int q   = warp * (BQ / 4) + r;
            const int tok = qt[b * BQ + q];
            float ssq = warp_sum(load_row_h(emb, tok,
                            reinterpret_cast<unsigned*>(qH) + q * (RSH / 2), lane));
            if (lane == 0) {
                rq[q] = 1.0f / (sqrtf(ssq) + 1e-13f);
                qtok[q] = tok;
            }
        }
    } else {
        const int pw = warp - 4;
        #pragma unroll 4
        for (int r = 0; r < DCH / 4; ++r) {
            const int dloc = pw * (DCH / 4) + r;      // 0..63 in buffer 0
            const int tok  = dt[b * BD + dloc];
            float ssq = warp_sum(load_row_h(emb, tok,
                            reinterpret_cast<unsigned*>(dH) + dloc * (RSH / 2), lane));
            if (lane == 0) {
                rd[dloc] = 1.0f / (sqrtf(ssq) + 1e-13f);
                dtok[dloc] = tok;
            }
        }
    }
    __syncthreads();

    // consumer mapping: mt = warp&1 (16 q rows), dh = warp>>1 (32 of 64 docs)
    const int mt = warp & 1;
    const int dh = warp >> 1;           // 0..1 (consumers only)

    const unsigned qBase = sm_u32(qH);
    const unsigned dBase = sm_u32(dH);
    const unsigned aAddr = qBase + (unsigned)(mt * 16 + (lane & 15)) * RSB
                                 + (unsigned)(lane >> 4) * 16;
    // paired-B ldmatrix.x4 base within a buffer
    const unsigned bAddr0 = dBase
        + (unsigned)(dh * 32 + ((lane >> 4) << 3) + (lane & 7)) * RSB
        + (unsigned)((lane >> 3) & 1) * 16;

    float kacc[2][NK];
    #pragma unroll
    for (int r = 0; r < 2; ++r)
        #pragma unroll
        for (int k = 0; k < NK; ++k) kacc[r][k] = 0.0f;

    const int gr  = lane >> 2;
    const int r0q = mt * 16 + gr;
    const int r1q = r0q + 8;
    const float rq0 = consumer ? rq[r0q] : 0.0f;
    const float rq1 = consumer ? rq[r1q] : 0.0f;
    const int   tq0 = consumer ? qtok[r0q] : 0;
    const int   tq1 = consumer ? qtok[r1q] : 0;

    for (int ch = 0; ch < NST; ++ch) {
        const int buf = ch & 1;

        if (consumer) {
            // ---- GEMM: m16 x 4 n8 tiles (2 pairs) over 19 k16 steps ----
            float C[4][4];
            #pragma unroll
            for (int t = 0; t < 4; ++t)
                #pragma unroll
                for (int i = 0; i < 4; ++i) C[t][i] = 0.0f;

            const unsigned bufOff = (unsigned)buf * (DCH * RSB);
            #pragma unroll 2
            for (int kk = 0; kk < KSTEPS; ++kk) {
                unsigned a0, a1, a2, a3;
                ldmx4(aAddr + kk * 32, a0, a1, a2, a3);
                #pragma unroll
                for (int p = 0; p < 2; ++p) {
                    unsigned b0, b1, b2, b3;
                    ldmx4(bAddr0 + bufOff + (unsigned)p * (16 * RSB) + kk * 32,
                          b0, b1, b2, b3);
                    mma16816(C[2 * p],     a0, a1, a2, a3, b0, b1);
                    mma16816(C[2 * p + 1], a0, a1, a2, a3, b2, b3);
                }
            }

            // ---- epilogue: RBF + exact-match over this warp's 32 docs ----
            #pragma unroll
            for (int t = 0; t < 4; ++t) {
                const int dloc = buf * DCH + dh * 32 + t * 8 + 2 * (lane & 3);
                #pragma unroll
                for (int cc = 0; cc < 2; ++cc) {
                    const float rdv = rd[dloc + cc];
                    const int   td  = dtok[dloc + cc];
                    rbf_acc(C[t][cc],     rq0, tq0, rdv, td, kacc[0]);
                    rbf_acc(C[t][cc + 2], rq1, tq1, rdv, td, kacc[1]);
                }
            }
        } else if (ch + 1 < NST) {
            // ---- producers: load stage ch+1 into the other buffer ----
            const int pw   = warp - 4;
            const int nbuf = (ch + 1) & 1;
            #pragma unroll 4
            for (int r = 0; r < DCH / 4; ++r) {
                const int dloc = nbuf * DCH + pw * (DCH / 4) + r;
                const int tok  = dt[b * BD + (ch + 1) * DCH + pw * (DCH / 4) + r];
                float ssq = warp_sum(load_row_h(emb, tok,
                                reinterpret_cast<unsigned*>(dH) + dloc * (RSH / 2), lane));
                if (lane == 0) {
                    rd[dloc] = 1.0f / (sqrtf(ssq) + 1e-13f);
                    dtok[dloc] = tok;
                }
            }
        }
        __syncthreads();
    }

    // ---- consumers: reduce kacc across the 4 lanes sharing a row group ----
    if (consumer) {
        #pragma unroll
        for (int r = 0; r < 2; ++r) {
            const int qrow = mt * 16 + gr + 8 * r;
            #pragma unroll
            for (int k = 0; k < NK; ++k) {
                float v = kacc[r][k];
                v += __shfl_xor_sync(0xffffffffu, v, 1);
                v += __shfl_xor_sync(0xffffffffu, v, 2);
                if ((lane & 3) == 0) atomicAdd(&qk[qrow * NK + k], v);
            }
        }
    }
    __syncthreads();

    // ---- log-pool over Q, FC, write score ----
    if (tid < BQ) {
        float s = 0.0f;
        #pragma unroll
        for (int k = 0; k < NK; ++k)
            s += fcw[k] * 0.01f * logf(fmaxf(qk[tid * NK + k], 1e-10f));
        s = warp_sum(s);
        if (lane == 0) out[b] = s + fcb[0];
    }
}

extern "C" void kernel_launch(void* const* d_in, const int* in_sizes, int n_in,
                              void* d_out, int out_size)
{
    const int*   qt  = (const int*)d_in[0];
    const int*   dt  = (const int*)d_in[1];
    const float* emb = (const float*)d_in[2];
    const float* fcw = (const float*)d_in[3];
    const float* fcb = (const float*)d_in[4];
    float* out = (float*)d_out;

    const int B = in_sizes[0] / BQ;   // 256

    const size_t smem = (size_t)(2 * DCH + BQ) * RSH * sizeof(__half)
                      + (size_t)(BQ + 2 * DCH) * sizeof(float)
                      + (size_t)(BQ + 2 * DCH) * sizeof(int)
                      + (size_t)(BQ * NK) * sizeof(float);   // 102,528 B
    cudaFuncSetAttribute(knrm_kernel,
                         cudaFuncAttributeMaxDynamicSharedMemorySize, (int)smem);
    knrm_kernel<<<B, NTH, smem>>>(qt, dt, emb, fcw, fcb, out);
}

// round 15
// speedup vs baseline: 1.8114x; 1.8114x over previous
#include <cuda_runtime.h>
#include <cuda_fp16.h>

#define BQ     32
#define BD     512
#define EDIM   300
#define NK     11
#define DCH    128
#define NCHUNK (BD / DCH)
#define RSH    312            // halfs per row (624 B = 39 granules, odd -> conflict-free)
#define RSB    (RSH * 2)      // bytes per row
#define KSTEPS 19             // K padded 300 -> 304 = 19*16
#define NTH    256

#define K50L2E   72.1347520f   //  50*log2(e)
#define C_B      129.8425536f  // 144.269504*0.9
#define C_R      28.8539008f   // 144.269504*0.2
#define C_RC     23.0831206f   // 28.8539008*0.9 - 2.88539008
#define C_TC0    58.4291492f   // 72.134752*0.81
#define C_STEP   0.0183156389f // e^-4

__device__ __forceinline__ float warp_sum(float v) {
    v += __shfl_xor_sync(0xffffffffu, v, 16);
    v += __shfl_xor_sync(0xffffffffu, v, 8);
    v += __shfl_xor_sync(0xffffffffu, v, 4);
    v += __shfl_xor_sync(0xffffffffu, v, 2);
    v += __shfl_xor_sync(0xffffffffu, v, 1);
    return v;
}

__device__ __forceinline__ unsigned sm_u32(const void* p) {
    unsigned r;
    asm("{ .reg .u64 t; cvta.to.shared.u64 t, %1; cvt.u32.u64 %0, t; }"
        : "=r"(r) : "l"(p));
    return r;
}

__device__ __forceinline__ float ex2(float x) {
    float r;
    asm("ex2.approx.f32 %0, %1;" : "=f"(r) : "f"(x));
    return r;
}

__device__ __forceinline__ void ldmx4(unsigned a, unsigned& r0, unsigned& r1,
                                      unsigned& r2, unsigned& r3) {
    asm volatile("ldmatrix.sync.aligned.m8n8.x4.shared.b16 {%0,%1,%2,%3}, [%4];"
                 : "=r"(r0), "=r"(r1), "=r"(r2), "=r"(r3) : "r"(a));
}

__device__ __forceinline__ void mma16816(float* C, unsigned a0, unsigned a1,
                                         unsigned a2, unsigned a3,
                                         unsigned b0, unsigned b1) {
    asm volatile("mma.sync.aligned.m16n8k16.row.col.f32.f16.f16.f32 "
                 "{%0,%1,%2,%3},{%4,%5,%6,%7},{%8,%9},{%0,%1,%2,%3};"
                 : "+f"(C[0]), "+f"(C[1]), "+f"(C[2]), "+f"(C[3])
                 : "r"(a0), "r"(a1), "r"(a2), "r"(a3), "r"(b0), "r"(b1));
}

// Streaming load: fp32 row -> fp16 smem row; per-lane ssq partial returned,
// NO shfl inside (keeps all row LDGs independent -> max MLP).
__device__ __forceinline__ float stream_row(const float* __restrict__ emb, int tok,
                                            unsigned* dstRow, int lane) {
    const float4* src = reinterpret_cast<const float4*>(emb) + (size_t)tok * (EDIM / 4);
    uint2* d8 = reinterpret_cast<uint2*>(dstRow);
    float ssq = 0.0f;
    float4 v;
    __half2 h0, h1;
    uint2 pk;

    v = src[lane];
    ssq += v.x*v.x + v.y*v.y + v.z*v.z + v.w*v.w;
    h0 = __floats2half2_rn(v.x, v.y); h1 = __floats2half2_rn(v.z, v.w);
    pk.x = *reinterpret_cast<unsigned*>(&h0); pk.y = *reinterpret_cast<unsigned*>(&h1);
    d8[lane] = pk;

    v = src[lane + 32];
    ssq += v.x*v.x + v.y*v.y + v.z*v.z + v.w*v.w;
    h0 = __floats2half2_rn(v.x, v.y); h1 = __floats2half2_rn(v.z, v.w);
    pk.x = *reinterpret_cast<unsigned*>(&h0); pk.y = *reinterpret_cast<unsigned*>(&h1);
    d8[lane + 32] = pk;

    if (lane < 11) {   // 75 float4 per row = 32 + 32 + 11
        v = src[lane + 64];
        ssq += v.x*v.x + v.y*v.y + v.z*v.z + v.w*v.w;
        h0 = __floats2half2_rn(v.x, v.y); h1 = __floats2half2_rn(v.z, v.w);
        pk.x = *reinterpret_cast<unsigned*>(&h0); pk.y = *reinterpret_cast<unsigned*>(&h1);
        d8[lane + 64] = pk;
    }
    return ssq;
}

// RBF via two telescoping Gaussian chains, 4 ex2; kernel 0 = exact token match.
__device__ __forceinline__ void rbf_acc(float c, float rqv, int tq, float rdv, int td,
                                        float* kacc) {
    const bool ok = (tq > 0) && (td > 0);
    if (ok && (tq == td)) kacc[0] += 1.0f;
    const float m    = c * (rqv * rdv);
    const float bias = ok ? -C_TC0 : -12000.0f;
    const float A258 = fmaf(-K50L2E * m, m, bias);
    float tA = ex2(fmaf( C_B, m, A258));
    float tB = ex2(fmaf(-C_B, m, A258));
    float rA = ex2(fmaf(-C_R, m, C_RC));
    float rB = ex2(fmaf( C_R, m, C_RC));
    kacc[1]  += tA;            kacc[10] += tB;
    tA *= rA;                  tB *= rB;
    kacc[2]  += tA;            kacc[9]  += tB;
    rA *= C_STEP;              rB *= C_STEP;
    tA *= rA;                  tB *= rB;
    kacc[3]  += tA;            kacc[8]  += tB;
    rA *= C_STEP;              rB *= C_STEP;
    tA *= rA;                  tB *= rB;
    kacc[4]  += tA;            kacc[7]  += tB;
    rA *= C_STEP;              rB *= C_STEP;
    tA *= rA;                  tB *= rB;
    kacc[5]  += tA;            kacc[6]  += tB;
}

__global__ __launch_bounds__(NTH, 2)
void knrm_kernel(const int* __restrict__ qt,
                 const int* __restrict__ dt,
                 const float* __restrict__ emb,
                 const float* __restrict__ fcw,
                 const float* __restrict__ fcb,
                 float* __restrict__ out)
{
    extern __shared__ __align__(16) unsigned char smraw[];
    __half* dH  = reinterpret_cast<__half*>(smraw);        // [DCH][RSH]
    __half* qH  = dH + DCH * RSH;                          // [BQ][RSH]
    float*  rq  = reinterpret_cast<float*>(qH + BQ * RSH); // [BQ]
    float*  rd  = rq + BQ;                                 // [DCH]
    int*    qtok = reinterpret_cast<int*>(rd + DCH);       // [BQ]
    int*    dtok = qtok + BQ;                              // [DCH]
    float*  qk  = reinterpret_cast<float*>(dtok + DCH);    // [BQ][NK]

    const int b    = blockIdx.x;
    const int tid  = threadIdx.x;
    const int lane = tid & 31;
    const int warp = tid >> 5;        // 0..7

    for (int i = tid; i < BQ * NK; i += NTH) qk[i] = 0.0f;

    // zero K-pad (halfs 300..311) for all 160 rows
    for (int i = tid; i < (DCH + BQ) * 3; i += NTH) {
        const int row = i / 3, j = i - row * 3;
        unsigned* base = (row < DCH) ? reinterpret_cast<unsigned*>(dH)
                                     : reinterpret_cast<unsigned*>(qH);
        const int r2 = (row < DCH) ? row : row - DCH;
        base[r2 * (RSH / 2) + 150 + j] = 0u;
    }

    // ---- q phase: 4 rows per warp, streamed, batched reductions ----
    {
        int tokv = 0;
        if (lane < BQ / 8)
            tokv = qt[b * BQ + warp * (BQ / 8) + lane];
        float ssqv[BQ / 8];
        #pragma unroll
        for (int r = 0; r < BQ / 8; ++r) {
            const int q   = warp * (BQ / 8) + r;
            const int tok = __shfl_sync(0xffffffffu, tokv, r);
            ssqv[r] = stream_row(emb, tok,
                          reinterpret_cast<unsigned*>(qH) + q * (RSH / 2), lane);
            if (lane == 0) qtok[q] = tok;
        }
        #pragma unroll
        for (int r = 0; r < BQ / 8; ++r) {
            const int q = warp * (BQ / 8) + r;
            float s = warp_sum(ssqv[r]);
            if (lane == 0) rq[q] = 1.0f / (sqrtf(s) + 1e-13f);
        }
    }

    // warp mapping: mt in {0,1} (16 q-rows), nq in [0,4) (32 docs = 2 tile-pairs)
    const int mt = warp & 1;
    const int nq = warp >> 1;

    const unsigned qBase = sm_u32(qH);
    const unsigned dBase = sm_u32(dH);
    const unsigned aAddr = qBase + (unsigned)(mt * 16 + (lane & 15)) * RSB
                                 + (unsigned)(lane >> 4) * 16;
    // paired-B ldmatrix.x4: mats = {tile 2p k0, tile 2p k8, tile 2p+1 k0, tile 2p+1 k8}
    const unsigned bAddrP = dBase
        + (unsigned)(nq * 32 + ((lane >> 4) << 3) + (lane & 7)) * RSB
        + (unsigned)((lane >> 3) & 1) * 16;

    float kacc[2][NK];
    #pragma unroll
    for (int r = 0; r < 2; ++r)
        #pragma unroll
        for (int k = 0; k < NK; ++k) kacc[r][k] = 0.0f;

    const int gr  = lane >> 2;
    const int r0q = mt * 16 + gr;
    const int r1q = r0q + 8;

    for (int ch = 0; ch < NCHUNK; ++ch) {
        __syncthreads();   // previous chunk readers done

        // ---- doc phase: 16 rows per warp, streamed, batched reductions ----
        {
            int tokv = 0;
            if (lane < DCH / 8)
                tokv = dt[b * BD + ch * DCH + warp * (DCH / 8) + lane];
            float ssqv[DCH / 8];
            #pragma unroll
            for (int r = 0; r < DCH / 8; ++r) {
                const int dloc = warp * (DCH / 8) + r;
                const int tok  = __shfl_sync(0xffffffffu, tokv, r);
                ssqv[r] = stream_row(emb, tok,
                              reinterpret_cast<unsigned*>(dH) + dloc * (RSH / 2), lane);
                if (lane == 0) dtok[dloc] = tok;
            }
            #pragma unroll
            for (int r = 0; r < DCH / 8; ++r) {
                const int dloc = warp * (DCH / 8) + r;
                float s = warp_sum(ssqv[r]);
                if (lane == 0) rd[dloc] = 1.0f / (sqrtf(s) + 1e-13f);
            }
        }
        __syncthreads();

        // ---- GEMM: 2 m16 x 2 tile-pairs per warp over 19 k16 steps ----
        float C[4][4];
        #pragma unroll
        for (int t = 0; t < 4; ++t)
            #pragma unroll
            for (int i = 0; i < 4; ++i) C[t][i] = 0.0f;

        #pragma unroll 2
        for (int kk = 0; kk < KSTEPS; ++kk) {
            unsigned a0, a1, a2, a3;
            ldmx4(aAddr + kk * 32, a0, a1, a2, a3);
            #pragma unroll
            for (int p = 0; p < 2; ++p) {
                unsigned b0, b1, b2, b3;
                ldmx4(bAddrP + (unsigned)p * (16 * RSB) + kk * 32, b0, b1, b2, b3);
                mma16816(C[2 * p],     a0, a1, a2, a3, b0, b1);
                mma16816(C[2 * p + 1], a0, a1, a2, a3, b2, b3);
            }
        }

        // ---- epilogue: RBF + exact-match count ----
        const float rq0 = rq[r0q];
        const float rq1 = rq[r1q];
        const int   tq0 = qtok[r0q];
        const int   tq1 = qtok[r1q];

        #pragma unroll
        for (int t = 0; t < 4; ++t) {
            const int cbase = nq * 32 + t * 8 + 2 * (lane & 3);
            #pragma unroll
            for (int cc = 0; cc < 2; ++cc) {
                const int d  = cbase + cc;
                const float rdv = rd[d];
                const int   td  = dtok[d];
                rbf_acc(C[t][cc],     rq0, tq0, rdv, td, kacc[0]);
                rbf_acc(C[t][cc + 2], rq1, tq1, rdv, td, kacc[1]);
            }
        }
    }

    // ---- reduce kacc across the 4 lanes sharing a row group, then smem atomics ----
    #pragma unroll
    for (int r = 0; r < 2; ++r) {
        const int qrow = mt * 16 + gr + 8 * r;
        #pragma unroll
        for (int k = 0; k < NK; ++k) {
            float v = kacc[r][k];
            v += __shfl_xor_sync(0xffffffffu, v, 1);
            v += __shfl_xor_sync(0xffffffffu, v, 2);
            if ((lane & 3) == 0) atomicAdd(&qk[qrow * NK + k], v);
        }
    }
    __syncthreads();

    // ---- log-pool over Q, FC, write score ----
    if (tid < BQ) {
        float s = 0.0f;
        #pragma unroll
        for (int k = 0; k < NK; ++k)
            s += fcw[k] * 0.01f * logf(fmaxf(qk[tid * NK + k], 1e-10f));
        s = warp_sum(s);
        if (lane == 0) out[b] = s + fcb[0];
    }
}

extern "C" void kernel_launch(void* const* d_in, const int* in_sizes, int n_in,
                              void* d_out, int out_size)
{
    const int*   qt  = (const int*)d_in[0];
    const int*   dt  = (const int*)d_in[1];
    const float* emb = (const float*)d_in[2];
    const float* fcw = (const float*)d_in[3];
    const float* fcb = (const float*)d_in[4];
    float* out = (float*)d_out;

    const int B = in_sizes[0] / BQ;   // 256

    const size_t smem = (size_t)(DCH + BQ) * RSH * sizeof(__half)
                      + (size_t)(BQ + DCH) * sizeof(float)
                      + (size_t)(BQ + DCH) * sizeof(int)
                      + (size_t)(BQ * NK) * sizeof(float);   // 102,528 B
    cudaFuncSetAttribute(knrm_kernel,
                         cudaFuncAttributeMaxDynamicSharedMemorySize, (int)smem);
    knrm_kernel<<<B, NTH, smem>>>(qt, dt, emb, fcw, fcb, out);
}

// round 17
// speedup vs baseline: 1.8804x; 1.0381x over previous
#include <cuda_runtime.h>
#include <cuda_fp16.h>

#define BQ     32
#define BD     512
#define EDIM   300
#define NK     11
#define DCH    128
#define NCHUNK (BD / DCH)
#define RSH    312            // halfs per row (624 B = 39 granules, odd -> conflict-free)
#define RSB    (RSH * 2)      // bytes per row
#define KSTEPS 19             // K padded 300 -> 304 = 19*16
#define NTH    512
#define NW     (NTH / 32)     // 16 warps

#define K50L2E   72.1347520f   //  50*log2(e)
#define C_B      129.8425536f  // 144.269504*0.9
#define C_R      28.8539008f   // 144.269504*0.2
#define C_RC     23.0831206f   // 28.8539008*0.9 - 2.88539008
#define C_TC0    58.4291492f   // 72.134752*0.81
#define C_STEP   0.0183156389f // e^-4

__device__ __forceinline__ float warp_sum(float v) {
    v += __shfl_xor_sync(0xffffffffu, v, 16);
    v += __shfl_xor_sync(0xffffffffu, v, 8);
    v += __shfl_xor_sync(0xffffffffu, v, 4);
    v += __shfl_xor_sync(0xffffffffu, v, 2);
    v += __shfl_xor_sync(0xffffffffu, v, 1);
    return v;
}

__device__ __forceinline__ unsigned sm_u32(const void* p) {
    unsigned r;
    asm("{ .reg .u64 t; cvta.to.shared.u64 t, %1; cvt.u32.u64 %0, t; }"
        : "=r"(r) : "l"(p));
    return r;
}

__device__ __forceinline__ float ex2(float x) {
    float r;
    asm("ex2.approx.f32 %0, %1;" : "=f"(r) : "f"(x));
    return r;
}

__device__ __forceinline__ void ldmx4(unsigned a, unsigned& r0, unsigned& r1,
                                      unsigned& r2, unsigned& r3) {
    asm volatile("ldmatrix.sync.aligned.m8n8.x4.shared.b16 {%0,%1,%2,%3}, [%4];"
                 : "=r"(r0), "=r"(r1), "=r"(r2), "=r"(r3) : "r"(a));
}

__device__ __forceinline__ void mma16816(float* C, unsigned a0, unsigned a1,
                                         unsigned a2, unsigned a3,
                                         unsigned b0, unsigned b1) {
    asm volatile("mma.sync.aligned.m16n8k16.row.col.f32.f16.f16.f32 "
                 "{%0,%1,%2,%3},{%4,%5,%6,%7},{%8,%9},{%0,%1,%2,%3};"
                 : "+f"(C[0]), "+f"(C[1]), "+f"(C[2]), "+f"(C[3])
                 : "r"(a0), "r"(a1), "r"(a2), "r"(a3), "r"(b0), "r"(b1));
}

// Streaming load: fp32 row -> fp16 smem row; per-lane ssq partial returned,
// NO shfl inside (keeps all row LDGs independent -> max MLP).
__device__ __forceinline__ float stream_row(const float* __restrict__ emb, int tok,
                                            unsigned* dstRow, int lane) {
    const float4* src = reinterpret_cast<const float4*>(emb) + (size_t)tok * (EDIM / 4);
    uint2* d8 = reinterpret_cast<uint2*>(dstRow);
    float ssq = 0.0f;
    float4 v;
    __half2 h0, h1;
    uint2 pk;

    v = src[lane];
    ssq += v.x*v.x + v.y*v.y + v.z*v.z + v.w*v.w;
    h0 = __floats2half2_rn(v.x, v.y); h1 = __floats2half2_rn(v.z, v.w);
    pk.x = *reinterpret_cast<unsigned*>(&h0); pk.y = *reinterpret_cast<unsigned*>(&h1);
    d8[lane] = pk;

    v = src[lane + 32];
    ssq += v.x*v.x + v.y*v.y + v.z*v.z + v.w*v.w;
    h0 = __floats2half2_rn(v.x, v.y); h1 = __floats2half2_rn(v.z, v.w);
    pk.x = *reinterpret_cast<unsigned*>(&h0); pk.y = *reinterpret_cast<unsigned*>(&h1);
    d8[lane + 32] = pk;

    if (lane < 11) {   // 75 float4 per row = 32 + 32 + 11
        v = src[lane + 64];
        ssq += v.x*v.x + v.y*v.y + v.z*v.z + v.w*v.w;
        h0 = __floats2half2_rn(v.x, v.y); h1 = __floats2half2_rn(v.z, v.w);
        pk.x = *reinterpret_cast<unsigned*>(&h0); pk.y = *reinterpret_cast<unsigned*>(&h1);
        d8[lane + 64] = pk;
    }
    return ssq;
}

// RBF via two telescoping Gaussian chains, 4 ex2; kernel 0 = exact token match.
__device__ __forceinline__ void rbf_acc(float c, float rqv, int tq, float rdv, int td,
                                        float* kacc) {
    const bool ok = (tq > 0) && (td > 0);
    if (ok && (tq == td)) kacc[0] += 1.0f;
    const float m    = c * (rqv * rdv);
    const float bias = ok ? -C_TC0 : -12000.0f;
    const float A258 = fmaf(-K50L2E * m, m, bias);
    float tA = ex2(fmaf( C_B, m, A258));
    float tB = ex2(fmaf(-C_B, m, A258));
    float rA = ex2(fmaf(-C_R, m, C_RC));
    float rB = ex2(fmaf( C_R, m, C_RC));
    kacc[1]  += tA;            kacc[10] += tB;
    tA *= rA;                  tB *= rB;
    kacc[2]  += tA;            kacc[9]  += tB;
    rA *= C_STEP;              rB *= C_STEP;
    tA *= rA;                  tB *= rB;
    kacc[3]  += tA;            kacc[8]  += tB;
    rA *= C_STEP;              rB *= C_STEP;
    tA *= rA;                  tB *= rB;
    kacc[4]  += tA;            kacc[7]  += tB;
    rA *= C_STEP;              rB *= C_STEP;
    tA *= rA;                  tB *= rB;
    kacc[5]  += tA;            kacc[6]  += tB;
}

__global__ __launch_bounds__(NTH, 2)
void knrm_kernel(const int* __restrict__ qt,
                 const int* __restrict__ dt,
                 const float* __restrict__ emb,
                 const float* __restrict__ fcw,
                 const float* __restrict__ fcb,
                 float* __restrict__ out)
{
    extern __shared__ __align__(16) unsigned char smraw[];
    __half* dH  = reinterpret_cast<__half*>(smraw);        // [DCH][RSH]
    __half* qH  = dH + DCH * RSH;                          // [BQ][RSH]
    float*  rq  = reinterpret_cast<float*>(qH + BQ * RSH); // [BQ]
    float*  rd  = rq + BQ;                                 // [DCH]
    int*    qtok = reinterpret_cast<int*>(rd + DCH);       // [BQ]
    int*    dtok = qtok + BQ;                              // [DCH]
    float*  qk  = reinterpret_cast<float*>(dtok + DCH);    // [BQ][NK]

    const int b    = blockIdx.x;
    const int tid  = threadIdx.x;
    const int lane = tid & 31;
    const int warp = tid >> 5;        // 0..15

    for (int i = tid; i < BQ * NK; i += NTH) qk[i] = 0.0f;

    // zero K-pad (halfs 300..311) for all 160 rows
    for (int i = tid; i < (DCH + BQ) * 3; i += NTH) {
        const int row = i / 3, j = i - row * 3;
        unsigned* base = (row < DCH) ? reinterpret_cast<unsigned*>(dH)
                                     : reinterpret_cast<unsigned*>(qH);
        const int r2 = (row < DCH) ? row : row - DCH;
        base[r2 * (RSH / 2) + 150 + j] = 0u;
    }

    // ---- q phase: 2 rows per warp, streamed, batched reductions ----
    {
        int tokv = 0;
        if (lane < BQ / NW)
            tokv = qt[b * BQ + warp * (BQ / NW) + lane];
        float ssqv[BQ / NW];
        #pragma unroll
        for (int r = 0; r < BQ / NW; ++r) {
            const int q   = warp * (BQ / NW) + r;
            const int tok = __shfl_sync(0xffffffffu, tokv, r);
            ssqv[r] = stream_row(emb, tok,
                          reinterpret_cast<unsigned*>(qH) + q * (RSH / 2), lane);
            if (lane == 0) qtok[q] = tok;
        }
        #pragma unroll
        for (int r = 0; r < BQ / NW; ++r) {
            const int q = warp * (BQ / NW) + r;
            float s = warp_sum(ssqv[r]);
            if (lane == 0) rq[q] = 1.0f / (sqrtf(s) + 1e-13f);
        }
    }

    // warp mapping: mt in {0,1} (16 q-rows), dh in [0,8) (16 docs = 1 tile-pair)
    const int mt = warp & 1;
    const int dh = warp >> 1;

    const unsigned qBase = sm_u32(qH);
    const unsigned dBase = sm_u32(dH);
    const unsigned aAddr = qBase + (unsigned)(mt * 16 + (lane & 15)) * RSB
                                 + (unsigned)(lane >> 4) * 16;
    // paired-B ldmatrix.x4: mats = {tile0 k0, tile0 k8, tile1 k0, tile1 k8}
    const unsigned bAddrP = dBase
        + (unsigned)(dh * 16 + ((lane >> 4) << 3) + (lane & 7)) * RSB
        + (unsigned)((lane >> 3) & 1) * 16;

    float kacc[2][NK];
    #pragma unroll
    for (int r = 0; r < 2; ++r)
        #pragma unroll
        for (int k = 0; k < NK; ++k) kacc[r][k] = 0.0f;

    const int gr  = lane >> 2;
    const int r0q = mt * 16 + gr;
    const int r1q = r0q + 8;

    for (int ch = 0; ch < NCHUNK; ++ch) {
        __syncthreads();   // previous chunk readers done

        // ---- doc phase: 8 rows per warp, streamed, batched reductions ----
        {
            int tokv = 0;
            if (lane < DCH / NW)
                tokv = dt[b * BD + ch * DCH + warp * (DCH / NW) + lane];
            float ssqv[DCH / NW];
            #pragma unroll
            for (int r = 0; r < DCH / NW; ++r) {
                const int dloc = warp * (DCH / NW) + r;
                const int tok  = __shfl_sync(0xffffffffu, tokv, r);
                ssqv[r] = stream_row(emb, tok,
                              reinterpret_cast<unsigned*>(dH) + dloc * (RSH / 2), lane);
                if (lane == 0) dtok[dloc] = tok;
            }
            #pragma unroll
            for (int r = 0; r < DCH / NW; ++r) {
                const int dloc = warp * (DCH / NW) + r;
                float s = warp_sum(ssqv[r]);
                if (lane == 0) rd[dloc] = 1.0f / (sqrtf(s) + 1e-13f);
            }
        }
        __syncthreads();

        // ---- GEMM: m16 x 1 tile-pair per warp over 19 k16 steps ----
        float C[2][4];
        #pragma unroll
        for (int t = 0; t < 2; ++t)
            #pragma unroll
            for (int i = 0; i < 4; ++i) C[t][i] = 0.0f;

        #pragma unroll 2
        for (int kk = 0; kk < KSTEPS; ++kk) {
            unsigned a0, a1, a2, a3;
            ldmx4(aAddr + kk * 32, a0, a1, a2, a3);
            unsigned b0, b1, b2, b3;
            ldmx4(bAddrP + kk * 32, b0, b1, b2, b3);
            mma16816(C[0], a0, a1, a2, a3, b0, b1);
            mma16816(C[1], a0, a1, a2, a3, b2, b3);
        }

        // ---- epilogue: RBF + exact-match count ----
        const float rq0 = rq[r0q];
        const float rq1 = rq[r1q];
        const int   tq0 = qtok[r0q];
        const int   tq1 = qtok[r1q];

        #pragma unroll
        for (int t = 0; t < 2; ++t) {
            const int cbase = dh * 16 + t * 8 + 2 * (lane & 3);
            #pragma unroll
            for (int cc = 0; cc < 2; ++cc) {
                const int d  = cbase + cc;
                const float rdv = rd[d];
                const int   td  = dtok[d];
                rbf_acc(C[t][cc],     rq0, tq0, rdv, td, kacc[0]);
                rbf_acc(C[t][cc + 2], rq1, tq1, rdv, td, kacc[1]);
            }
        }
    }

    // ---- reduce kacc across the 4 lanes sharing a row group, then smem atomics ----
    #pragma unroll
    for (int r = 0; r < 2; ++r) {
        const int qrow = mt * 16 + gr + 8 * r;
        #pragma unroll
        for (int k = 0; k < NK; ++k) {
            float v = kacc[r][k];
            v += __shfl_xor_sync(0xffffffffu, v, 1);
            v += __shfl_xor_sync(0xffffffffu, v, 2);
            if ((lane & 3) == 0) atomicAdd(&qk[qrow * NK + k], v);
        }
    }
    __syncthreads();

    // ---- log-pool over Q, FC, write score ----
    if (tid < BQ) {
        float s = 0.0f;
        #pragma unroll
        for (int k = 0; k < NK; ++k)
            s += fcw[k] * 0.01f * logf(fmaxf(qk[tid * NK + k], 1e-10f));
        s = warp_sum(s);
        if (lane == 0) out[b] = s + fcb[0];
    }
}

extern "C" void kernel_launch(void* const* d_in, const int* in_sizes, int n_in,
                              void* d_out, int out_size)
{
    const int*   qt  = (const int*)d_in[0];
    const int*   dt  = (const int*)d_in[1];
    const float* emb = (const float*)d_in[2];
    const float* fcw = (const float*)d_in[3];
    const float* fcb = (const float*)d_in[4];
    float* out = (float*)d_out;

    const int B = in_sizes[0] / BQ;   // 256

    const size_t smem = (size_t)(DCH + BQ) * RSH * sizeof(__half)
                      + (size_t)(BQ + DCH) * sizeof(float)
                      + (size_t)(BQ + DCH) * sizeof(int)
                      + (size_t)(BQ * NK) * sizeof(float);   // 102,528 B
    cudaFuncSetAttribute(knrm_kernel,
                         cudaFuncAttributeMaxDynamicSharedMemorySize, (int)smem);
    knrm_kernel<<<B, NTH, smem>>>(qt, dt, emb, fcw, fcb, out);
}